// round 16
// baseline (speedup 1.0000x reference)
#include <cuda_runtime.h>
#include <cuda_fp16.h>
#include <math.h>
#include <stdint.h>

// Problem constants
#define BB   8
#define LL   3072
#define DD   1024
#define TOPK 8
#define NF   1537          // LL/2 + 1
#define CHB  8             // channels per FFT block

#define MTOT (BB * LL)     // 24576

// ---------------------------------------------------------------------------
// Static device scratch
// ---------------------------------------------------------------------------
__device__ __half g_Qt[(size_t)BB * DD * LL];     // q projected, fp16, [B][D][L]
__device__ __half g_Kt[(size_t)BB * DD * LL];     // k projected, fp16, [B][D][L]
__device__ float  g_V [(size_t)BB * LL * DD];     // Y = V@Wo + bo, [B][L][D]
__device__ float2 g_P[(size_t)BB * (DD / CHB) * NF];  // partial spectra
__device__ float2 g_S[BB * NF];
__device__ float2 g_tw[LL];
__device__ float  g_w[BB * TOPK];
__device__ int    g_d[BB * TOPK];
// fp16 A operands (single limb): regions 0..2. asplit writes Q->0, K->1,
// V->2. V-projection epilogue writes fp16(V) into region 0 for the Y-GEMM.
__device__ __align__(16) __half g_Ah[(size_t)3 * MTOT * DD];
__device__ __align__(16) __half g_Bh[(size_t)4 * DD * DD];   // Bh[n][k] = W[k][n]

// ---------------------------------------------------------------------------
// PTX helpers (all base-ISA; no 'a'-suffix features)
// ---------------------------------------------------------------------------
__device__ __forceinline__ uint32_t smem_u32(const void* p) {
    uint32_t a;
    asm("{ .reg .u64 t; cvta.to.shared.u64 t, %1; cvt.u32.u64 %0, t; }"
        : "=r"(a) : "l"(p));
    return a;
}
__device__ __forceinline__ void cp16(uint32_t s, const void* g) {
    asm volatile("cp.async.cg.shared.global [%0], [%1], 16;" :: "r"(s), "l"(g));
}
__device__ __forceinline__ void cp_commit() {
    asm volatile("cp.async.commit_group;");
}
// Not volatile — pure data ops; lets the scheduler hoist/interleave.
__device__ __forceinline__ void ldmx4(uint32_t* r, uint32_t a) {
    asm("ldmatrix.sync.aligned.m8n8.x4.shared.b16 {%0,%1,%2,%3}, [%4];"
        : "=r"(r[0]), "=r"(r[1]), "=r"(r[2]), "=r"(r[3]) : "r"(a));
}
__device__ __forceinline__ void mma16816(float* d, const uint32_t* a,
                                         uint32_t b0, uint32_t b1) {
    asm("mma.sync.aligned.m16n8k16.row.col.f32.f16.f16.f32 "
        "{%0,%1,%2,%3}, {%4,%5,%6,%7}, {%8,%9}, {%0,%1,%2,%3};"
        : "+f"(d[0]), "+f"(d[1]), "+f"(d[2]), "+f"(d[3])
        : "r"(a[0]), "r"(a[1]), "r"(a[2]), "r"(a[3]), "r"(b0), "r"(b1));
}
__device__ __forceinline__ uint32_t packh2(__half a, __half b) {
    __half2 t = __halves2half2(a, b);
    return *(uint32_t*)&t;
}

// ---------------------------------------------------------------------------
// Weight transpose + fp16 convert:  Bh[n][k] = fp16(W[k][n])
// ---------------------------------------------------------------------------
__global__ void k_wconv(const float* __restrict__ W0, const float* __restrict__ W1,
                        const float* __restrict__ W2, const float* __restrict__ W3)
{
    __shared__ float t[32][33];
    int z = blockIdx.z;
    const float* W = (z == 0) ? W0 : (z == 1) ? W1 : (z == 2) ? W2 : W3;
    __half* Bh = g_Bh + (size_t)z * DD * DD;
    int n0 = blockIdx.x * 32, k0 = blockIdx.y * 32;
    int tx = threadIdx.x, ty = threadIdx.y;
#pragma unroll
    for (int j = 0; j < 32; j += 8)
        t[ty + j][tx] = W[(size_t)(k0 + ty + j) * DD + n0 + tx];
    __syncthreads();
#pragma unroll
    for (int j = 0; j < 32; j += 8)
        Bh[(size_t)(n0 + ty + j) * DD + k0 + tx] = __float2half_rn(t[tx][ty + j]);
}

// ---------------------------------------------------------------------------
// A convert for Q,K,V in one launch: fp32 -> fp16 into region blockIdx.y.
// ---------------------------------------------------------------------------
__global__ __launch_bounds__(256) void k_asplit3(
    const float4* __restrict__ X0, const float4* __restrict__ X1,
    const float4* __restrict__ X2)
{
    const int reg = blockIdx.y;
    const float4* X = (reg == 0) ? X0 : (reg == 1) ? X1 : X2;
    size_t i = (size_t)blockIdx.x * 256 + threadIdx.x;
    float4 v = X[i];
    __half h0 = __float2half_rn(v.x), h1 = __float2half_rn(v.y);
    __half h2 = __float2half_rn(v.z), h3 = __float2half_rn(v.w);
    size_t o = (size_t)reg * (MTOT * DD / 4) + i;
    ((uint2*)g_Ah)[o] = make_uint2(packh2(h0, h1), packh2(h2, h3));
}

// ---------------------------------------------------------------------------
// Tensor-core GEMM (mma.sync fp16, single limb):
//   C[m][n] = sum_k Ah[m][k] * Bh[n][k]  + bias[n]
// CTA tile 128x128, 512 threads = 16 warps (4m x 4n), warp tile 32x32
// (acc = 32 regs -> room for FRAGMENT DOUBLE-BUFFERING: ks+1 LDSMs issue
// before ks's MMAs so the scoreboard wait hides behind 8 MMAs).
// KC=64 (4 k16 steps), 3-stage cp.async pipeline, chunk c+2 loads spread
// across the 4 ks-steps of chunk c.
// SMEM/stage 32KB: A[16KB] B[16KB]; 128B rows, 16B-seg XOR swizzle.
// zsel: derive (areg,widx,mode) from blockIdx.z (fused Q/K/V launch).
// modes: 0/1 -> fp16 transposed g_Qt/g_Kt; 2 -> fp16 region 0 (V-proj);
//        3 -> float natural into g_V (Y = V@Wo + bo).
// ---------------------------------------------------------------------------
#define KC 64
#define NCH (DD / KC)      // 16 chunks
#define OFF_B  16384
#define BUF_SZ 32768
#define NSTG 3

__global__ __launch_bounds__(512, 1)
void k_gemm(int areg, int widx, const float* __restrict__ bias0,
            const float* __restrict__ bias1, const float* __restrict__ bias2,
            int mode, int zsel)
{
    extern __shared__ __align__(16) char smem[];
    __shared__ float s_bias[128];

    if (zsel) { areg = blockIdx.z; widx = blockIdx.z; mode = blockIdx.z; }
    const float* bias = (widx == 1) ? bias1 : (widx == 2) ? bias2 : bias0;

    const int tid  = threadIdx.x;
    const int wid  = tid >> 5;
    const int lane = tid & 31;
    const int n0 = blockIdx.x * 128;
    const int m0 = blockIdx.y * 128;
    const int mw = wid >> 2;      // 0..3
    const int nw = wid & 3;       // 0..3

    const __half* Ah = g_Ah + (size_t)areg * MTOT * DD;
    const __half* Bh = g_Bh + (size_t)widx * DD * DD;

    if (tid < 128) s_bias[tid] = bias[n0 + tid];

    const uint32_t sbase = smem_u32(smem);

    float acc[2][4][4];
#pragma unroll
    for (int i = 0; i < 2; i++)
#pragma unroll
        for (int j = 0; j < 4; j++)
#pragma unroll
            for (int q = 0; q < 4; q++) acc[i][j][q] = 0.0f;

    // one quarter (512 of 2048 16B-lines) of a chunk's loads
    auto load_quarter = [&](int k0n, uint32_t sbn, int ks) {
        int idx = ks * 512 + tid;        // [0, 2048)
        if (idx < 1024) {
            int row = idx >> 3, seg = idx & 7;
            uint32_t so = (uint32_t)(row * 128 + ((seg ^ (row & 7)) * 16));
            cp16(sbn + so, Ah + (size_t)(m0 + row) * DD + k0n + seg * 8);
        } else {
            int j = idx - 1024;
            int row = j >> 3, seg = j & 7;
            uint32_t so = (uint32_t)(row * 128 + ((seg ^ (row & 7)) * 16));
            cp16(sbn + OFF_B + so, Bh + (size_t)(n0 + row) * DD + k0n + seg * 8);
        }
    };
    auto load_chunk = [&](int c, int b) {
        uint32_t sb = sbase + b * BUF_SZ;
#pragma unroll
        for (int ks = 0; ks < 4; ks++) load_quarter(c * KC, sb, ks);
        cp_commit();
    };

    // fragment loader (warp tile 32x32: 2 A + 2 B ldmx4 per ks)
    uint32_t aF[2][2][4], bF[2][2][4];
    const int arow0 = mw * 32 + (lane & 15);
    const int nrow0 = nw * 32 + ((lane >> 4) & 1) * 8 + (lane & 7);
    auto ldfr = [&](int ks, uint32_t bufu, int sl) {
        const int sega = ks * 2 + (lane >> 4);
#pragma unroll
        for (int mi = 0; mi < 2; mi++) {
            int row = arow0 + mi * 16;
            ldmx4(aF[sl][mi], bufu + row * 128 + ((sega ^ (row & 7)) * 16));
        }
        const int segb = ks * 2 + ((lane >> 3) & 1);
#pragma unroll
        for (int gi = 0; gi < 2; gi++) {
            int nrow = nrow0 + gi * 16;
            ldmx4(bF[sl][gi], bufu + OFF_B + nrow * 128 + ((segb ^ (nrow & 7)) * 16));
        }
    };

    load_chunk(0, 0);
    load_chunk(1, 1);

    int bufc = 0;   // c % 3
    for (int c = 0; c < NCH; c++) {
        if (c + 1 < NCH) {
            asm volatile("cp.async.wait_group 1;");
        } else {
            asm volatile("cp.async.wait_group 0;");
        }
        __syncthreads();

        const uint32_t bufu = sbase + bufc * BUF_SZ;
        const int cn = c + 2;                      // chunk being prefetched
        int bn = bufc + 2; if (bn >= NSTG) bn -= NSTG;
        const uint32_t sbn = sbase + bn * BUF_SZ;
        const bool pf = (cn < NCH);

        ldfr(0, bufu, 0);
#pragma unroll
        for (int ks = 0; ks < 4; ks++) {
            const int cur = ks & 1;
            if (ks < 3) ldfr(ks + 1, bufu, cur ^ 1);
            if (pf) load_quarter(cn * KC, sbn, ks);
#pragma unroll
            for (int gi = 0; gi < 2; gi++)
#pragma unroll
                for (int half = 0; half < 2; half++)
#pragma unroll
                    for (int mi = 0; mi < 2; mi++)
                        mma16816(acc[mi][gi * 2 + half], aF[cur][mi],
                                 bF[cur][gi][half * 2], bF[cur][gi][half * 2 + 1]);
        }
        if (pf) cp_commit();
        bufc = (bufc + 1 == NSTG) ? 0 : bufc + 1;
    }
    __syncthreads();

    // ---- Epilogue: stage C tile (128 x 132 fp32) in smem, write coalesced ----
    float* smemC = (float*)smem;
#pragma unroll
    for (int mi = 0; mi < 2; mi++) {
        int r0 = mw * 32 + mi * 16 + (lane >> 2);
#pragma unroll
        for (int ni = 0; ni < 4; ni++) {
            int col = nw * 32 + ni * 8 + (lane & 3) * 2;
            smemC[r0 * 132 + col]           = acc[mi][ni][0];
            smemC[r0 * 132 + col + 1]       = acc[mi][ni][1];
            smemC[(r0 + 8) * 132 + col]     = acc[mi][ni][2];
            smemC[(r0 + 8) * 132 + col + 1] = acc[mi][ni][3];
        }
    }
    __syncthreads();

    if (mode <= 1) {
        // fp16 transposed output: col-major over [B][D][L]
        __half* dstT = (mode == 0) ? g_Qt : g_Kt;
        const int bB = m0 / LL;
        const int s0 = m0 - bB * LL;
#pragma unroll
        for (int i = 0; i < 8; i++) {
            int col = wid * 8 + i;
            float bi = s_bias[col];
            __half h0 = __float2half_rn(smemC[(lane * 4 + 0) * 132 + col] + bi);
            __half h1 = __float2half_rn(smemC[(lane * 4 + 1) * 132 + col] + bi);
            __half h2 = __float2half_rn(smemC[(lane * 4 + 2) * 132 + col] + bi);
            __half h3 = __float2half_rn(smemC[(lane * 4 + 3) * 132 + col] + bi);
            *(uint2*)&dstT[((size_t)bB * DD + n0 + col) * LL + s0 + lane * 4] =
                make_uint2(packh2(h0, h1), packh2(h2, h3));
        }
    } else if (mode == 2) {
        // V projection: write fp16(C + bias) into region 0 for the Y-GEMM
        const int row = tid >> 2;
        const int cb  = (tid & 3) * 32;
        const size_t rb = (size_t)(m0 + row) * DD + n0 + cb;
#pragma unroll
        for (int i = 0; i < 8; i++) {
            float4 v = *(float4*)&smemC[row * 132 + cb + i * 4];
            v.x += s_bias[cb + i * 4 + 0];
            v.y += s_bias[cb + i * 4 + 1];
            v.z += s_bias[cb + i * 4 + 2];
            v.w += s_bias[cb + i * 4 + 3];
            __half h0 = __float2half_rn(v.x), h1 = __float2half_rn(v.y);
            __half h2 = __float2half_rn(v.z), h3 = __float2half_rn(v.w);
            *(uint2*)(g_Ah + rb + i * 4) = make_uint2(packh2(h0, h1), packh2(h2, h3));
        }
    } else {
        // Y = V @ Wo + bo, float natural layout into g_V
        const int row = tid >> 2;
        const int cb  = (tid & 3) * 32;
        const size_t rb = (size_t)(m0 + row) * DD + n0 + cb;
#pragma unroll
        for (int i = 0; i < 8; i++) {
            float4 v = *(float4*)&smemC[row * 132 + cb + i * 4];
            v.x += s_bias[cb + i * 4 + 0];
            v.y += s_bias[cb + i * 4 + 1];
            v.z += s_bias[cb + i * 4 + 2];
            v.w += s_bias[cb + i * 4 + 3];
            *(float4*)&g_V[rb + i * 4] = v;
        }
    }
}

// ---------------------------------------------------------------------------
// Twiddle init
// ---------------------------------------------------------------------------
__global__ void k_twiddle() {
    int j = blockIdx.x * blockDim.x + threadIdx.x;
    if (j < LL) {
        double a = -6.283185307179586476925286766559 * (double)j / (double)LL;
        g_tw[j] = make_float2((float)cos(a), (float)sin(a));
    }
}

// ---------------------------------------------------------------------------
// Mixed-radix Stockham FFT: five radix-4 stages (s = 4^j, shift/mask
// indexing, stage-invariant coalesced reads) then one twiddle-free radix-3
// stage (p = 0). SGN=+1 forward, SGN=-1 inverse (unnormalized). Ends in p0.
// ---------------------------------------------------------------------------
__device__ __forceinline__ float2 cmul(float2 a, float2 b) {
    return make_float2(a.x * b.x - a.y * b.y, a.x * b.y + a.y * b.x);
}

template <int SGN>
__device__ float2* block_fft(float2* p0, float2* p1, int tid, int nt)
{
    float2* px = p0;
    float2* py = p1;
#pragma unroll
    for (int j = 0; j < 5; j++) {
        const int s = 1 << (2 * j);
        for (int t = tid; t < 768; t += nt) {
            int q = t & (s - 1);
            int base = t - q;                 // p * s
            float2 a = px[t];
            float2 b = px[t + 768];
            float2 c = px[t + 1536];
            float2 d = px[t + 2304];
            float t0r = a.x + c.x, t0i = a.y + c.y;
            float t1r = a.x - c.x, t1i = a.y - c.y;
            float t2r = b.x + d.x, t2i = b.y + d.y;
            float t3r = b.x - d.x, t3i = b.y - d.y;
            float y1r, y1i, y3r, y3i;
            if (SGN > 0) { y1r = t1r + t3i; y1i = t1i - t3r;
                           y3r = t1r - t3i; y3i = t1i + t3r; }
            else         { y1r = t1r - t3i; y1i = t1i + t3r;
                           y3r = t1r + t3i; y3i = t1i - t3r; }
            float2 w1 = g_tw[base];        if (SGN < 0) w1.y = -w1.y;
            float2 w2 = g_tw[2 * base];    if (SGN < 0) w2.y = -w2.y;
            float2 w3 = g_tw[3 * base];    if (SGN < 0) w3.y = -w3.y;
            int o = 4 * base + q;
            py[o]         = make_float2(t0r + t2r, t0i + t2i);
            py[o + s]     = cmul(make_float2(y1r, y1i), w1);
            py[o + 2 * s] = cmul(make_float2(t0r - t2r, t0i - t2i), w2);
            py[o + 3 * s] = cmul(make_float2(y3r, y3i), w3);
        }
        __syncthreads();
        float2* tp = px; px = py; py = tp;
    }
    // final radix-3 stage: s=1024, m=1 -> p=0, twiddle-free
    {
        const float s0 = (SGN > 0) ? -0.86602540378443864676f
                                   :  0.86602540378443864676f;
        for (int q = tid; q < 1024; q += nt) {
            float2 a = px[q], b = px[q + 1024], c = px[q + 2048];
            float ur = b.x + c.x, ui = b.y + c.y;
            float dr = b.x - c.x, di = b.y - c.y;
            float vr = a.x - 0.5f * ur, vi = a.y - 0.5f * ui;
            float wr = -s0 * di, wi = s0 * dr;
            py[q]        = make_float2(a.x + ur, a.y + ui);
            py[q + 1024] = make_float2(vr + wr, vi + wi);
            py[q + 2048] = make_float2(vr - wr, vi - wi);
        }
        __syncthreads();
    }
    return py;   // 5 swaps: px==p1 after loop; radix-3 writes py==p0
}

// ---------------------------------------------------------------------------
// Forward FFT of q,k packed as z = q + i*k for CHB=8 channels per block,
// with the channel reduction fused (one partial spectrum per block).
// q/k read as fp16. grid = BB*DD/CHB = 1024, 256 threads, 61.5KB smem.
// ---------------------------------------------------------------------------
__global__ __launch_bounds__(256) void k_fft()
{
    extern __shared__ __align__(16) float2 fsm[];
    float2* p0   = fsm;            // [0, LL)
    float2* p1   = fsm + LL;       // [LL, 2LL)
    float2* accS = fsm + 2 * LL;   // [2LL, 2LL+NF)

    const int blk = blockIdx.x;            // 0..1023
    const int tid = threadIdx.x;

    for (int f = tid; f < NF; f += 256) accS[f] = make_float2(0.f, 0.f);

    for (int ch = 0; ch < CHB; ch++) {
        size_t bc = (size_t)blk * CHB + ch;
        const __half* qr = g_Qt + bc * LL;
        const __half* kr = g_Kt + bc * LL;
        __syncthreads();   // previous iteration's accS readers done with p0
        for (int i = tid; i < LL; i += 256)
            p0[i] = make_float2(__half2float(qr[i]), __half2float(kr[i]));
        __syncthreads();

        float2* z = block_fft<1>(p0, p1, tid, 256);   // z == p0

        for (int f = tid; f < NF; f += 256) {
            float2 zf = z[f];
            int ridx = (f == 0) ? 0 : (LL - f);
            float2 zr = z[ridx];
            float qre = 0.5f * (zf.x + zr.x);
            float qim = 0.5f * (zf.y - zr.y);
            float dr = zf.x - zr.x;
            float di = zf.y + zr.y;
            float kre = 0.5f * di;
            float kim = -0.5f * dr;
            float2 a = accS[f];
            a.x += qre * kre + qim * kim;
            a.y += qim * kre - qre * kim;
            accS[f] = a;
        }
    }
    __syncthreads();
    float2* P = g_P + (size_t)blk * NF;
    for (int f = tid; f < NF; f += 256) P[f] = accS[f];
}

// ---------------------------------------------------------------------------
// Deterministic reduction over the 128 partials per batch:
//   S[b,f] = sum_p P[b,p,f]
// ---------------------------------------------------------------------------
#define NPART (DD / CHB)   // 128
__global__ __launch_bounds__(256) void k_reduce()
{
    __shared__ float red[2][8][32];
    const int b    = blockIdx.y;
    const int lane = threadIdx.x & 31;
    const int cw   = threadIdx.x >> 5;
    const int f    = blockIdx.x * 32 + lane;

    float sr = 0.0f, si = 0.0f;
    if (f < NF) {
        for (int p = cw; p < NPART; p += 8) {
            float2 v = g_P[((size_t)b * NPART + p) * NF + f];
            sr += v.x; si += v.y;
        }
    }
    red[0][cw][lane] = sr;
    red[1][cw][lane] = si;
    __syncthreads();
    if (cw == 0 && f < NF) {
        float ar = 0.0f, ai = 0.0f;
#pragma unroll
        for (int w = 0; w < 8; w++) { ar += red[0][w][lane]; ai += red[1][w][lane]; }
        g_S[b * NF + f] = make_float2(ar, ai);
    }
}

// ---------------------------------------------------------------------------
// Per-batch inverse FFT -> mean_value, top-8 + softmax
// ---------------------------------------------------------------------------
__global__ __launch_bounds__(512) void k_ifft_topk()
{
    __shared__ __align__(16) float2 pool[2 * LL];
    float2* p0 = pool;
    float2* p1 = pool + LL;

    const int b = blockIdx.x;
    const int tid = threadIdx.x;
    const int nt = 512;

    for (int f = tid; f < LL; f += nt) {
        float2 v;
        if (f < NF) v = g_S[b * NF + f];
        else {
            float2 u = g_S[b * NF + (LL - f)];
            v = make_float2(u.x, -u.y);
        }
        p0[f] = v;
    }
    __syncthreads();

    float2* z = block_fft<-1>(p0, p1, tid, nt);   // z == p0

    // scratch lives in p1 (z occupies p0)
    float* meanArr = (float*)(pool + LL);
    float* redV    = meanArr + 3072;
    int*   redI    = (int*)(meanArr + 3584);

    const float scale = 1.0f / ((float)LL * (float)DD);
    for (int i = tid; i < LL; i += nt) meanArr[i] = z[i].x * scale;
    __syncthreads();

    float lw[TOPK];
    int   ld[TOPK];
    for (int k = 0; k < TOPK; k++) {
        float bv = -1e30f;
        int   bi = 0x7fffffff;
        for (int i = tid; i < LL; i += nt) {
            float v = meanArr[i];
            if (v > bv || (v == bv && i < bi)) { bv = v; bi = i; }
        }
        redV[tid] = bv; redI[tid] = bi;
        __syncthreads();
        for (int off = 256; off > 0; off >>= 1) {
            if (tid < off) {
                float v2 = redV[tid + off];
                int   i2 = redI[tid + off];
                if (v2 > redV[tid] || (v2 == redV[tid] && i2 < redI[tid])) {
                    redV[tid] = v2; redI[tid] = i2;
                }
            }
            __syncthreads();
        }
        if (tid == 0) {
            lw[k] = redV[0];
            ld[k] = redI[0];
            meanArr[redI[0]] = -1e30f;
        }
        __syncthreads();
    }

    if (tid == 0) {
        float mx = lw[0];
        for (int i = 1; i < TOPK; i++) mx = fmaxf(mx, lw[i]);
        float e[TOPK];
        float sum = 0.0f;
        for (int i = 0; i < TOPK; i++) { e[i] = expf(lw[i] - mx); sum += e[i]; }
        for (int i = 0; i < TOPK; i++) {
            g_w[b * TOPK + i] = e[i] / sum;
            g_d[b * TOPK + i] = ld[i];
        }
    }
}

// ---------------------------------------------------------------------------
// Time-delay aggregation over Y (Y already includes Wo and bo; sum w_i = 1):
//   Out[b][s][c] = sum_i w[b,i] * Y[b][(s+d_i)%L][c]
// ---------------------------------------------------------------------------
__global__ __launch_bounds__(256) void k_agg(float* __restrict__ Out)
{
    __shared__ float ws[TOPK];
    __shared__ int   ds[TOPK];
    const int s = blockIdx.x;
    const int b = blockIdx.y;
    const int tid = threadIdx.x;
    if (tid < TOPK) { ws[tid] = g_w[b * TOPK + tid]; ds[tid] = g_d[b * TOPK + tid]; }
    __syncthreads();

    const float* Yb = g_V + (size_t)b * LL * DD;
    const int c = tid * 4;
    float4 acc = make_float4(0.f, 0.f, 0.f, 0.f);
#pragma unroll
    for (int i = 0; i < TOPK; i++) {
        int j = s + ds[i];
        if (j >= LL) j -= LL;
        float4 v = *(const float4*)(Yb + (size_t)j * DD + c);
        float w = ws[i];
        acc.x += w * v.x; acc.y += w * v.y; acc.z += w * v.z; acc.w += w * v.w;
    }
    *(float4*)(Out + ((size_t)b * LL + s) * DD + c) = acc;
}

// ---------------------------------------------------------------------------
// kernel_launch
// ---------------------------------------------------------------------------
extern "C" void kernel_launch(void* const* d_in, const int* in_sizes, int n_in,
                              void* d_out, int out_size)
{
    const float* queries = (const float*)d_in[0];
    const float* keys    = (const float*)d_in[1];
    const float* values  = (const float*)d_in[2];
    const float* Wq = (const float*)d_in[3];
    const float* bq = (const float*)d_in[4];
    const float* Wk = (const float*)d_in[5];
    const float* bk = (const float*)d_in[6];
    const float* Wv = (const float*)d_in[7];
    const float* bv = (const float*)d_in[8];
    const float* Wo = (const float*)d_in[9];
    const float* bo = (const float*)d_in[10];
    float* Out = (float*)d_out;

    (void)in_sizes; (void)n_in; (void)out_size;

    const int dynG = NSTG * BUF_SZ;               // 98304 (> epilogue 67584)
    const int dynF = 2 * LL * 8 + NF * 8;         // 61448
    cudaFuncSetAttribute(k_gemm, cudaFuncAttributeMaxDynamicSharedMemorySize, dynG);
    cudaFuncSetAttribute(k_fft,  cudaFuncAttributeMaxDynamicSharedMemorySize, dynF);

    k_twiddle<<<(LL + 255) / 256, 256>>>();
    k_wconv<<<dim3(32, 32, 4), dim3(32, 8)>>>(Wq, Wk, Wv, Wo);

    const int nsplit = (int)((size_t)MTOT * DD / 1024);   // 24576 blocks
    k_asplit3<<<dim3(nsplit, 3), 256>>>((const float4*)queries,
                                        (const float4*)keys,
                                        (const float4*)values);

    // fused Q/K/V projection GEMMs (z selects operand set + output mode;
    // V-proj writes fp16(V) into region 0)
    k_gemm<<<dim3(DD / 128, MTOT / 128, 3), 512, dynG>>>(
        0, 0, bq, bk, bv, 0, 1);

    // Y = V @ Wo + bo (region 0) -> g_V
    k_gemm<<<dim3(DD / 128, MTOT / 128, 1), 512, dynG>>>(
        0, 3, bo, bo, bo, 3, 0);

    k_fft<<<BB * DD / CHB, 256, dynF>>>();
    k_reduce<<<dim3((NF + 31) / 32, BB), 256>>>();
    k_ifft_topk<<<BB, 512>>>();
    k_agg<<<dim3(LL, BB), 256>>>(Out);
}

// round 17
// speedup vs baseline: 1.2029x; 1.2029x over previous
#include <cuda_runtime.h>
#include <cuda_fp16.h>
#include <math.h>
#include <stdint.h>

// Problem constants
#define BB   8
#define LL   3072
#define DD   1024
#define TOPK 8
#define NF   1537          // LL/2 + 1
#define CHB  8             // channels per FFT block

#define MTOT (BB * LL)     // 24576

// ---------------------------------------------------------------------------
// Static device scratch
// ---------------------------------------------------------------------------
__device__ __half g_Qt[(size_t)BB * DD * LL];     // q projected, fp16, [B][D][L]
__device__ __half g_Kt[(size_t)BB * DD * LL];     // k projected, fp16, [B][D][L]
__device__ float  g_V [(size_t)BB * LL * DD];     // Y = V@Wo + bo, [B][L][D]
__device__ float2 g_P[(size_t)BB * (DD / CHB) * NF];  // partial spectra
__device__ float2 g_S[BB * NF];
__device__ float2 g_tw[LL];
__device__ float  g_w[BB * TOPK];
__device__ int    g_d[BB * TOPK];
// fp16 A operands (single limb): regions 0..2. asplit writes Q->0, K->1,
// V->2. V-projection epilogue writes fp16(V) into region 0 for the Y-GEMM.
__device__ __align__(16) __half g_Ah[(size_t)3 * MTOT * DD];
__device__ __align__(16) __half g_Bh[(size_t)4 * DD * DD];   // Bh[n][k] = W[k][n]

// ---------------------------------------------------------------------------
// PTX helpers (all base-ISA; no 'a'-suffix features)
// ---------------------------------------------------------------------------
__device__ __forceinline__ uint32_t smem_u32(const void* p) {
    uint32_t a;
    asm("{ .reg .u64 t; cvta.to.shared.u64 t, %1; cvt.u32.u64 %0, t; }"
        : "=r"(a) : "l"(p));
    return a;
}
__device__ __forceinline__ void cp16(uint32_t s, const void* g) {
    asm volatile("cp.async.cg.shared.global [%0], [%1], 16;" :: "r"(s), "l"(g));
}
__device__ __forceinline__ void cp_commit() {
    asm volatile("cp.async.commit_group;");
}
// Not volatile — pure data ops; lets the scheduler hoist/interleave.
__device__ __forceinline__ void ldmx4(uint32_t* r, uint32_t a) {
    asm("ldmatrix.sync.aligned.m8n8.x4.shared.b16 {%0,%1,%2,%3}, [%4];"
        : "=r"(r[0]), "=r"(r[1]), "=r"(r[2]), "=r"(r[3]) : "r"(a));
}
__device__ __forceinline__ void mma16816(float* d, const uint32_t* a,
                                         uint32_t b0, uint32_t b1) {
    asm("mma.sync.aligned.m16n8k16.row.col.f32.f16.f16.f32 "
        "{%0,%1,%2,%3}, {%4,%5,%6,%7}, {%8,%9}, {%0,%1,%2,%3};"
        : "+f"(d[0]), "+f"(d[1]), "+f"(d[2]), "+f"(d[3])
        : "r"(a[0]), "r"(a[1]), "r"(a[2]), "r"(a[3]), "r"(b0), "r"(b1));
}
__device__ __forceinline__ uint32_t packh2(__half a, __half b) {
    __half2 t = __halves2half2(a, b);
    return *(uint32_t*)&t;
}

// ---------------------------------------------------------------------------
// Weight transpose + fp16 convert:  Bh[n][k] = fp16(W[k][n])
// ---------------------------------------------------------------------------
__global__ void k_wconv(const float* __restrict__ W0, const float* __restrict__ W1,
                        const float* __restrict__ W2, const float* __restrict__ W3)
{
    __shared__ float t[32][33];
    int z = blockIdx.z;
    const float* W = (z == 0) ? W0 : (z == 1) ? W1 : (z == 2) ? W2 : W3;
    __half* Bh = g_Bh + (size_t)z * DD * DD;
    int n0 = blockIdx.x * 32, k0 = blockIdx.y * 32;
    int tx = threadIdx.x, ty = threadIdx.y;
#pragma unroll
    for (int j = 0; j < 32; j += 8)
        t[ty + j][tx] = W[(size_t)(k0 + ty + j) * DD + n0 + tx];
    __syncthreads();
#pragma unroll
    for (int j = 0; j < 32; j += 8)
        Bh[(size_t)(n0 + ty + j) * DD + k0 + tx] = __float2half_rn(t[tx][ty + j]);
}

// ---------------------------------------------------------------------------
// A convert for Q,K,V in one launch: fp32 -> fp16 into region blockIdx.y.
// ---------------------------------------------------------------------------
__global__ __launch_bounds__(256) void k_asplit3(
    const float4* __restrict__ X0, const float4* __restrict__ X1,
    const float4* __restrict__ X2)
{
    const int reg = blockIdx.y;
    const float4* X = (reg == 0) ? X0 : (reg == 1) ? X1 : X2;
    size_t i = (size_t)blockIdx.x * 256 + threadIdx.x;
    float4 v = X[i];
    __half h0 = __float2half_rn(v.x), h1 = __float2half_rn(v.y);
    __half h2 = __float2half_rn(v.z), h3 = __float2half_rn(v.w);
    size_t o = (size_t)reg * (MTOT * DD / 4) + i;
    ((uint2*)g_Ah)[o] = make_uint2(packh2(h0, h1), packh2(h2, h3));
}

// ---------------------------------------------------------------------------
// Tensor-core GEMM (mma.sync fp16, single limb) — round-15 config restored:
//   C[m][n] = sum_k Ah[m][k] * Bh[n][k]  + bias[n]
// CTA tile 128x128, 256 threads = 8 warps (4m x 2n), warp tile 32x64,
// 16 distinct accumulators/warp, 2 CTAs/SM (two independent barrier domains).
// KC=64 (4 k16 steps), 3-stage cp.async pipeline, chunk c+2 loads spread
// across the 4 ks-steps of chunk c (smooth LSU occupancy).
// SMEM/stage 32KB: A[16KB] B[16KB]; 128B rows, 16B-seg XOR swizzle.
// zsel: derive (areg,widx,mode) from blockIdx.z (fused Q/K/V launch).
// modes: 0/1 -> fp16 transposed g_Qt/g_Kt; 2 -> fp16 region 0 (V-proj);
//        3 -> float natural into g_V (Y = V@Wo + bo).
// ---------------------------------------------------------------------------
#define KC 64
#define NCH (DD / KC)      // 16 chunks
#define OFF_B  16384
#define BUF_SZ 32768
#define NSTG 3

__global__ __launch_bounds__(256, 2)
void k_gemm(int areg, int widx, const float* __restrict__ bias0,
            const float* __restrict__ bias1, const float* __restrict__ bias2,
            int mode, int zsel)
{
    extern __shared__ __align__(16) char smem[];
    __shared__ float s_bias[128];

    if (zsel) { areg = blockIdx.z; widx = blockIdx.z; mode = blockIdx.z; }
    const float* bias = (widx == 1) ? bias1 : (widx == 2) ? bias2 : bias0;

    const int tid  = threadIdx.x;
    const int wid  = tid >> 5;
    const int lane = tid & 31;
    const int n0 = blockIdx.x * 128;
    const int m0 = blockIdx.y * 128;
    const int mw = wid >> 1;      // 0..3
    const int nw = wid & 1;       // 0..1

    const __half* Ah = g_Ah + (size_t)areg * MTOT * DD;
    const __half* Bh = g_Bh + (size_t)widx * DD * DD;

    if (tid < 128) s_bias[tid] = bias[n0 + tid];

    const uint32_t sbase = smem_u32(smem);

    float acc[2][8][4];
#pragma unroll
    for (int i = 0; i < 2; i++)
#pragma unroll
        for (int j = 0; j < 8; j++)
#pragma unroll
            for (int q = 0; q < 4; q++) acc[i][j][q] = 0.0f;

    // one quarter (256 of 1024 16B-lines per array) of chunk loads
    auto load_quarter = [&](int k0n, uint32_t sbn, int ks) {
        int idx = ks * 256 + tid;        // [0, 1024)
        int row = idx >> 3;
        int seg = idx & 7;
        uint32_t so = (uint32_t)(row * 128 + ((seg ^ (row & 7)) * 16));
        cp16(sbn + so,         Ah + (size_t)(m0 + row) * DD + k0n + seg * 8);
        cp16(sbn + OFF_B + so, Bh + (size_t)(n0 + row) * DD + k0n + seg * 8);
    };
    auto load_chunk = [&](int c, int b) {
        uint32_t sb = sbase + b * BUF_SZ;
#pragma unroll
        for (int ks = 0; ks < 4; ks++) load_quarter(c * KC, sb, ks);
        cp_commit();
    };

    load_chunk(0, 0);
    load_chunk(1, 1);

    int bufc = 0;   // c % 3
    for (int c = 0; c < NCH; c++) {
        if (c + 1 < NCH) {
            asm volatile("cp.async.wait_group 1;");
        } else {
            asm volatile("cp.async.wait_group 0;");
        }
        __syncthreads();

        const uint32_t bufu = sbase + bufc * BUF_SZ;
        const int cn = c + 2;                      // chunk being prefetched
        int bn = bufc + 2; if (bn >= NSTG) bn -= NSTG;
        const uint32_t sbn = sbase + bn * BUF_SZ;
        const bool pf = (cn < NCH);

#pragma unroll
        for (int ks = 0; ks < 4; ks++) {
            uint32_t a1f[2][4];
            const int arow0 = mw * 32 + (lane & 15);
            const int sega  = ks * 2 + (lane >> 4);
#pragma unroll
            for (int mi = 0; mi < 2; mi++) {
                int row = arow0 + mi * 16;
                ldmx4(a1f[mi], bufu + row * 128 + ((sega ^ (row & 7)) * 16));
            }
            const int nrow0 = nw * 64 + ((lane >> 4) & 1) * 8 + (lane & 7);
            const int segb  = ks * 2 + ((lane >> 3) & 1);
            uint32_t bf[4][4];
#pragma unroll
            for (int gi = 0; gi < 4; gi++) {
                int nrow = nrow0 + gi * 16;
                ldmx4(bf[gi], bufu + OFF_B + nrow * 128 + ((segb ^ (nrow & 7)) * 16));
            }
            // interleave one quarter of the c+2 prefetch with this ks's MMAs
            if (pf) load_quarter(cn * KC, sbn, ks);
#pragma unroll
            for (int gi = 0; gi < 4; gi++)
#pragma unroll
                for (int half = 0; half < 2; half++)
#pragma unroll
                    for (int mi = 0; mi < 2; mi++)
                        mma16816(acc[mi][gi * 2 + half], a1f[mi],
                                 bf[gi][half * 2], bf[gi][half * 2 + 1]);
        }
        if (pf) cp_commit();
        bufc = (bufc + 1 == NSTG) ? 0 : bufc + 1;
    }
    __syncthreads();

    // ---- Epilogue: stage C tile (128 x 132 fp32) in smem, write coalesced ----
    float* smemC = (float*)smem;
#pragma unroll
    for (int mi = 0; mi < 2; mi++) {
        int r0 = mw * 32 + mi * 16 + (lane >> 2);
#pragma unroll
        for (int ni = 0; ni < 8; ni++) {
            int col = nw * 64 + ni * 8 + (lane & 3) * 2;
            smemC[r0 * 132 + col]           = acc[mi][ni][0];
            smemC[r0 * 132 + col + 1]       = acc[mi][ni][1];
            smemC[(r0 + 8) * 132 + col]     = acc[mi][ni][2];
            smemC[(r0 + 8) * 132 + col + 1] = acc[mi][ni][3];
        }
    }
    __syncthreads();

    if (mode <= 1) {
        // fp16 transposed output: [B][D][L]
        __half* dstT = (mode == 0) ? g_Qt : g_Kt;
        const int bB = m0 / LL;
        const int s0 = m0 - bB * LL;
#pragma unroll
        for (int i = 0; i < 16; i++) {
            int col = wid * 16 + i;
            float bi = s_bias[col];
            __half h0 = __float2half_rn(smemC[(lane * 4 + 0) * 132 + col] + bi);
            __half h1 = __float2half_rn(smemC[(lane * 4 + 1) * 132 + col] + bi);
            __half h2 = __float2half_rn(smemC[(lane * 4 + 2) * 132 + col] + bi);
            __half h3 = __float2half_rn(smemC[(lane * 4 + 3) * 132 + col] + bi);
            *(uint2*)&dstT[((size_t)bB * DD + n0 + col) * LL + s0 + lane * 4] =
                make_uint2(packh2(h0, h1), packh2(h2, h3));
        }
    } else if (mode == 2) {
        // V projection: write fp16(C + bias) into region 0 for the Y-GEMM
        const int row = tid >> 1;
        const int cb  = (tid & 1) * 64;
        const size_t rb = (size_t)(m0 + row) * DD + n0 + cb;
#pragma unroll
        for (int i = 0; i < 16; i++) {
            float4 v = *(float4*)&smemC[row * 132 + cb + i * 4];
            v.x += s_bias[cb + i * 4 + 0];
            v.y += s_bias[cb + i * 4 + 1];
            v.z += s_bias[cb + i * 4 + 2];
            v.w += s_bias[cb + i * 4 + 3];
            __half h0 = __float2half_rn(v.x), h1 = __float2half_rn(v.y);
            __half h2 = __float2half_rn(v.z), h3 = __float2half_rn(v.w);
            *(uint2*)(g_Ah + rb + i * 4) = make_uint2(packh2(h0, h1), packh2(h2, h3));
        }
    } else {
        // Y = V @ Wo + bo, float natural layout into g_V
        const int row = tid >> 1;
        const int cb  = (tid & 1) * 64;
        const size_t rb = (size_t)(m0 + row) * DD + n0 + cb;
#pragma unroll
        for (int i = 0; i < 16; i++) {
            float4 v = *(float4*)&smemC[row * 132 + cb + i * 4];
            v.x += s_bias[cb + i * 4 + 0];
            v.y += s_bias[cb + i * 4 + 1];
            v.z += s_bias[cb + i * 4 + 2];
            v.w += s_bias[cb + i * 4 + 3];
            *(float4*)&g_V[rb + i * 4] = v;
        }
    }
}

// ---------------------------------------------------------------------------
// Twiddle init
// ---------------------------------------------------------------------------
__global__ void k_twiddle() {
    int j = blockIdx.x * blockDim.x + threadIdx.x;
    if (j < LL) {
        double a = -6.283185307179586476925286766559 * (double)j / (double)LL;
        g_tw[j] = make_float2((float)cos(a), (float)sin(a));
    }
}

// ---------------------------------------------------------------------------
// Mixed-radix Stockham FFT: five radix-4 stages (s = 4^j, shift/mask
// indexing, stage-invariant coalesced reads) then one twiddle-free radix-3
// stage (p = 0). SGN=+1 forward, SGN=-1 inverse (unnormalized). Ends in p0.
// ---------------------------------------------------------------------------
__device__ __forceinline__ float2 cmul(float2 a, float2 b) {
    return make_float2(a.x * b.x - a.y * b.y, a.x * b.y + a.y * b.x);
}

template <int SGN>
__device__ float2* block_fft(float2* p0, float2* p1, int tid, int nt)
{
    float2* px = p0;
    float2* py = p1;
#pragma unroll
    for (int j = 0; j < 5; j++) {
        const int s = 1 << (2 * j);
        for (int t = tid; t < 768; t += nt) {
            int q = t & (s - 1);
            int base = t - q;                 // p * s
            float2 a = px[t];
            float2 b = px[t + 768];
            float2 c = px[t + 1536];
            float2 d = px[t + 2304];
            float t0r = a.x + c.x, t0i = a.y + c.y;
            float t1r = a.x - c.x, t1i = a.y - c.y;
            float t2r = b.x + d.x, t2i = b.y + d.y;
            float t3r = b.x - d.x, t3i = b.y - d.y;
            float y1r, y1i, y3r, y3i;
            if (SGN > 0) { y1r = t1r + t3i; y1i = t1i - t3r;
                           y3r = t1r - t3i; y3i = t1i + t3r; }
            else         { y1r = t1r - t3i; y1i = t1i + t3r;
                           y3r = t1r + t3i; y3i = t1i - t3r; }
            float2 w1 = g_tw[base];        if (SGN < 0) w1.y = -w1.y;
            float2 w2 = g_tw[2 * base];    if (SGN < 0) w2.y = -w2.y;
            float2 w3 = g_tw[3 * base];    if (SGN < 0) w3.y = -w3.y;
            int o = 4 * base + q;
            py[o]         = make_float2(t0r + t2r, t0i + t2i);
            py[o + s]     = cmul(make_float2(y1r, y1i), w1);
            py[o + 2 * s] = cmul(make_float2(t0r - t2r, t0i - t2i), w2);
            py[o + 3 * s] = cmul(make_float2(y3r, y3i), w3);
        }
        __syncthreads();
        float2* tp = px; px = py; py = tp;
    }
    // final radix-3 stage: s=1024, m=1 -> p=0, twiddle-free
    {
        const float s0 = (SGN > 0) ? -0.86602540378443864676f
                                   :  0.86602540378443864676f;
        for (int q = tid; q < 1024; q += nt) {
            float2 a = px[q], b = px[q + 1024], c = px[q + 2048];
            float ur = b.x + c.x, ui = b.y + c.y;
            float dr = b.x - c.x, di = b.y - c.y;
            float vr = a.x - 0.5f * ur, vi = a.y - 0.5f * ui;
            float wr = -s0 * di, wi = s0 * dr;
            py[q]        = make_float2(a.x + ur, a.y + ui);
            py[q + 1024] = make_float2(vr + wr, vi + wi);
            py[q + 2048] = make_float2(vr - wr, vi - wi);
        }
        __syncthreads();
    }
    return py;   // 5 swaps: px==p1 after loop; radix-3 writes py==p0
}

// ---------------------------------------------------------------------------
// Forward FFT of q,k packed as z = q + i*k for CHB=8 channels per block,
// with the channel reduction fused (one partial spectrum per block).
// q/k read as fp16. grid = BB*DD/CHB = 1024, 256 threads, 61.5KB smem.
// ---------------------------------------------------------------------------
__global__ __launch_bounds__(256) void k_fft()
{
    extern __shared__ __align__(16) float2 fsm[];
    float2* p0   = fsm;            // [0, LL)
    float2* p1   = fsm + LL;       // [LL, 2LL)
    float2* accS = fsm + 2 * LL;   // [2LL, 2LL+NF)

    const int blk = blockIdx.x;            // 0..1023
    const int tid = threadIdx.x;

    for (int f = tid; f < NF; f += 256) accS[f] = make_float2(0.f, 0.f);

    for (int ch = 0; ch < CHB; ch++) {
        size_t bc = (size_t)blk * CHB + ch;
        const __half* qr = g_Qt + bc * LL;
        const __half* kr = g_Kt + bc * LL;
        __syncthreads();   // previous iteration's accS readers done with p0
        for (int i = tid; i < LL; i += 256)
            p0[i] = make_float2(__half2float(qr[i]), __half2float(kr[i]));
        __syncthreads();

        float2* z = block_fft<1>(p0, p1, tid, 256);   // z == p0

        for (int f = tid; f < NF; f += 256) {
            float2 zf = z[f];
            int ridx = (f == 0) ? 0 : (LL - f);
            float2 zr = z[ridx];
            float qre = 0.5f * (zf.x + zr.x);
            float qim = 0.5f * (zf.y - zr.y);
            float dr = zf.x - zr.x;
            float di = zf.y + zr.y;
            float kre = 0.5f * di;
            float kim = -0.5f * dr;
            float2 a = accS[f];
            a.x += qre * kre + qim * kim;
            a.y += qim * kre - qre * kim;
            accS[f] = a;
        }
    }
    __syncthreads();
    float2* P = g_P + (size_t)blk * NF;
    for (int f = tid; f < NF; f += 256) P[f] = accS[f];
}

// ---------------------------------------------------------------------------
// Deterministic reduction over the 128 partials per batch:
//   S[b,f] = sum_p P[b,p,f]
// ---------------------------------------------------------------------------
#define NPART (DD / CHB)   // 128
__global__ __launch_bounds__(256) void k_reduce()
{
    __shared__ float red[2][8][32];
    const int b    = blockIdx.y;
    const int lane = threadIdx.x & 31;
    const int cw   = threadIdx.x >> 5;
    const int f    = blockIdx.x * 32 + lane;

    float sr = 0.0f, si = 0.0f;
    if (f < NF) {
        for (int p = cw; p < NPART; p += 8) {
            float2 v = g_P[((size_t)b * NPART + p) * NF + f];
            sr += v.x; si += v.y;
        }
    }
    red[0][cw][lane] = sr;
    red[1][cw][lane] = si;
    __syncthreads();
    if (cw == 0 && f < NF) {
        float ar = 0.0f, ai = 0.0f;
#pragma unroll
        for (int w = 0; w < 8; w++) { ar += red[0][w][lane]; ai += red[1][w][lane]; }
        g_S[b * NF + f] = make_float2(ar, ai);
    }
}

// ---------------------------------------------------------------------------
// Per-batch inverse FFT -> mean_value, top-8 + softmax
// ---------------------------------------------------------------------------
__global__ __launch_bounds__(512) void k_ifft_topk()
{
    __shared__ __align__(16) float2 pool[2 * LL];
    float2* p0 = pool;
    float2* p1 = pool + LL;

    const int b = blockIdx.x;
    const int tid = threadIdx.x;
    const int nt = 512;

    for (int f = tid; f < LL; f += nt) {
        float2 v;
        if (f < NF) v = g_S[b * NF + f];
        else {
            float2 u = g_S[b * NF + (LL - f)];
            v = make_float2(u.x, -u.y);
        }
        p0[f] = v;
    }
    __syncthreads();

    float2* z = block_fft<-1>(p0, p1, tid, nt);   // z == p0

    // scratch lives in p1 (z occupies p0)
    float* meanArr = (float*)(pool + LL);
    float* redV    = meanArr + 3072;
    int*   redI    = (int*)(meanArr + 3584);

    const float scale = 1.0f / ((float)LL * (float)DD);
    for (int i = tid; i < LL; i += nt) meanArr[i] = z[i].x * scale;
    __syncthreads();

    float lw[TOPK];
    int   ld[TOPK];
    for (int k = 0; k < TOPK; k++) {
        float bv = -1e30f;
        int   bi = 0x7fffffff;
        for (int i = tid; i < LL; i += nt) {
            float v = meanArr[i];
            if (v > bv || (v == bv && i < bi)) { bv = v; bi = i; }
        }
        redV[tid] = bv; redI[tid] = bi;
        __syncthreads();
        for (int off = 256; off > 0; off >>= 1) {
            if (tid < off) {
                float v2 = redV[tid + off];
                int   i2 = redI[tid + off];
                if (v2 > redV[tid] || (v2 == redV[tid] && i2 < redI[tid])) {
                    redV[tid] = v2; redI[tid] = i2;
                }
            }
            __syncthreads();
        }
        if (tid == 0) {
            lw[k] = redV[0];
            ld[k] = redI[0];
            meanArr[redI[0]] = -1e30f;
        }
        __syncthreads();
    }

    if (tid == 0) {
        float mx = lw[0];
        for (int i = 1; i < TOPK; i++) mx = fmaxf(mx, lw[i]);
        float e[TOPK];
        float sum = 0.0f;
        for (int i = 0; i < TOPK; i++) { e[i] = expf(lw[i] - mx); sum += e[i]; }
        for (int i = 0; i < TOPK; i++) {
            g_w[b * TOPK + i] = e[i] / sum;
            g_d[b * TOPK + i] = ld[i];
        }
    }
}

// ---------------------------------------------------------------------------
// Time-delay aggregation over Y (Y already includes Wo and bo; sum w_i = 1):
//   Out[b][s][c] = sum_i w[b,i] * Y[b][(s+d_i)%L][c]
// ---------------------------------------------------------------------------
__global__ __launch_bounds__(256) void k_agg(float* __restrict__ Out)
{
    __shared__ float ws[TOPK];
    __shared__ int   ds[TOPK];
    const int s = blockIdx.x;
    const int b = blockIdx.y;
    const int tid = threadIdx.x;
    if (tid < TOPK) { ws[tid] = g_w[b * TOPK + tid]; ds[tid] = g_d[b * TOPK + tid]; }
    __syncthreads();

    const float* Yb = g_V + (size_t)b * LL * DD;
    const int c = tid * 4;
    float4 acc = make_float4(0.f, 0.f, 0.f, 0.f);
#pragma unroll
    for (int i = 0; i < TOPK; i++) {
        int j = s + ds[i];
        if (j >= LL) j -= LL;
        float4 v = *(const float4*)(Yb + (size_t)j * DD + c);
        float w = ws[i];
        acc.x += w * v.x; acc.y += w * v.y; acc.z += w * v.z; acc.w += w * v.w;
    }
    *(float4*)(Out + ((size_t)b * LL + s) * DD + c) = acc;
}

// ---------------------------------------------------------------------------
// kernel_launch
// ---------------------------------------------------------------------------
extern "C" void kernel_launch(void* const* d_in, const int* in_sizes, int n_in,
                              void* d_out, int out_size)
{
    const float* queries = (const float*)d_in[0];
    const float* keys    = (const float*)d_in[1];
    const float* values  = (const float*)d_in[2];
    const float* Wq = (const float*)d_in[3];
    const float* bq = (const float*)d_in[4];
    const float* Wk = (const float*)d_in[5];
    const float* bk = (const float*)d_in[6];
    const float* Wv = (const float*)d_in[7];
    const float* bv = (const float*)d_in[8];
    const float* Wo = (const float*)d_in[9];
    const float* bo = (const float*)d_in[10];
    float* Out = (float*)d_out;

    (void)in_sizes; (void)n_in; (void)out_size;

    const int dynG = NSTG * BUF_SZ;               // 98304 (> epilogue 67584)
    const int dynF = 2 * LL * 8 + NF * 8;         // 61448
    cudaFuncSetAttribute(k_gemm, cudaFuncAttributeMaxDynamicSharedMemorySize, dynG);
    cudaFuncSetAttribute(k_fft,  cudaFuncAttributeMaxDynamicSharedMemorySize, dynF);

    k_twiddle<<<(LL + 255) / 256, 256>>>();
    k_wconv<<<dim3(32, 32, 4), dim3(32, 8)>>>(Wq, Wk, Wv, Wo);

    const int nsplit = (int)((size_t)MTOT * DD / 1024);   // 24576 blocks
    k_asplit3<<<dim3(nsplit, 3), 256>>>((const float4*)queries,
                                        (const float4*)keys,
                                        (const float4*)values);

    // fused Q/K/V projection GEMMs (z selects operand set + output mode;
    // V-proj writes fp16(V) into region 0)
    k_gemm<<<dim3(DD / 128, MTOT / 128, 3), 256, dynG>>>(
        0, 0, bq, bk, bv, 0, 1);

    // Y = V @ Wo + bo (region 0) -> g_V
    k_gemm<<<dim3(DD / 128, MTOT / 128, 1), 256, dynG>>>(
        0, 3, bo, bo, bo, 3, 0);

    k_fft<<<BB * DD / CHB, 256, dynF>>>();
    k_reduce<<<dim3((NF + 31) / 32, BB), 256>>>();
    k_ifft_topk<<<BB, 512>>>();
    k_agg<<<dim3(LL, BB), 256>>>(Out);
}